// round 1
// baseline (speedup 1.0000x reference)
#include <cuda_runtime.h>
#include <cstdint>
#include <math.h>

#define KK   3
#define CIN  512
#define COUT 512
#define WDIM 512
#define NB   16
#define HW   64

#define CONV_COEF 0.014731391274719739f   /* 1/sqrt(9*512) */
#define FC_COEF   0.044194173824159216f   /* 1/sqrt(512)   */

/* ------------------------------------------------------------------ */
/* scratch (no cudaMalloc allowed -> __device__ globals)               */
/* ------------------------------------------------------------------ */
__device__ float g_xs[(size_t)NB * HW * HW * CIN];  /* x*s, tf32-rounded, NHWC */
__device__ float g_wt[KK * KK * CIN * COUT];        /* coef*w, tf32-rounded    */
__device__ float g_s[NB * CIN];                     /* style                   */
__device__ float g_d[NB * COUT];                    /* demod                   */
__device__ float g_wsq[CIN * COUT];                 /* sum_k w^2               */

__device__ __forceinline__ float tf32r(float x) {
    uint32_t u;
    asm("cvt.rna.tf32.f32 %0, %1;" : "=r"(u) : "f"(x));
    return __uint_as_float(u);
}

/* ------------------------------------------------------------------ */
/* prep kernels                                                        */
/* ------------------------------------------------------------------ */
__global__ void style_kernel(const float* __restrict__ wl,
                             const float* __restrict__ fcw,
                             const float* __restrict__ fcb) {
    int b = blockIdx.x;
    int i = threadIdx.x;
    float acc = 0.f;
    for (int j = 0; j < WDIM; j++)
        acc = fmaf(wl[b * WDIM + j], fcw[j * CIN + i], acc);
    g_s[b * CIN + i] = acc * FC_COEF + fcb[i] + 1.0f;
}

__global__ void prepw_kernel(const float* __restrict__ w) {
    int idx = blockIdx.x * 256 + threadIdx.x;   /* float4 groups */
    float4 v = ((const float4*)w)[idx];
    v.x = tf32r(v.x * CONV_COEF);
    v.y = tf32r(v.y * CONV_COEF);
    v.z = tf32r(v.z * CONV_COEF);
    v.w = tf32r(v.w * CONV_COEF);
    ((float4*)g_wt)[idx] = v;
}

__global__ void wsq_kernel(const float* __restrict__ w) {
    int idx = blockIdx.x * 256 + threadIdx.x;   /* (ci,co) pair */
    float acc = 0.f;
#pragma unroll
    for (int t9 = 0; t9 < 9; t9++) {
        float v = w[t9 * CIN * COUT + idx];
        acc = fmaf(v, v, acc);
    }
    g_wsq[idx] = acc;
}

__global__ void modx_kernel(const float* __restrict__ x) {
    int idx = blockIdx.x * 256 + threadIdx.x;   /* float4 groups over [b][y][x][c] */
    int cg  = idx & (CIN / 4 - 1);
    int bhw = idx >> 7;
    int b   = bhw >> 12;                         /* / (64*64) */
    float4 xv = ((const float4*)x)[idx];
    float4 sv = *(const float4*)(g_s + b * CIN + cg * 4);
    float4 o;
    o.x = tf32r(xv.x * sv.x);
    o.y = tf32r(xv.y * sv.y);
    o.z = tf32r(xv.z * sv.z);
    o.w = tf32r(xv.w * sv.w);
    ((float4*)g_xs)[idx] = o;
}

__global__ void demod_kernel() {
    int b  = blockIdx.x;
    int co = threadIdx.x;
    float acc = 0.f;
    for (int ci = 0; ci < CIN; ci++) {
        float s = g_s[b * CIN + ci];
        acc = fmaf(s * s, g_wsq[ci * COUT + co], acc);
    }
    g_d[b * COUT + co] = rsqrtf(acc * CONV_COEF * CONV_COEF + 1e-8f);
}

/* ------------------------------------------------------------------ */
/* implicit-GEMM conv (tf32 mma.sync)                                  */
/* ------------------------------------------------------------------ */
#define BM   128      /* 2 image rows x 64 */
#define BN   128
#define BKC  16       /* cin chunk */
#define CP   20       /* x-tile c pitch (== 4 mod 32 -> conflict-free frags) */
#define XPW  66       /* x positions incl halo */
#define WP   136      /* W pitch (== 8 mod 32 -> conflict-free frags) */

__device__ __forceinline__ void mma_tf32(float* c, const uint32_t* a, const uint32_t* b) {
    asm volatile(
        "mma.sync.aligned.m16n8k8.row.col.f32.tf32.tf32.f32 "
        "{%0,%1,%2,%3}, {%4,%5,%6,%7}, {%8,%9}, {%0,%1,%2,%3};"
        : "+f"(c[0]), "+f"(c[1]), "+f"(c[2]), "+f"(c[3])
        : "r"(a[0]), "r"(a[1]), "r"(a[2]), "r"(a[3]), "r"(b[0]), "r"(b[1]));
}

__global__ __launch_bounds__(256, 2) void conv_kernel(const float* __restrict__ bias,
                                                      float* __restrict__ out) {
    __shared__ float xsm[4 * XPW * CP];   /* [row 4][xp 66][c 16] pitch 20 */
    __shared__ float wsm[BKC * WP];       /* [c 16][n 128] pitch 136 */

    const int nblk = blockIdx.x;            /* 0..3   */
    const int rblk = blockIdx.y;            /* 0..511 */
    const int b    = rblk >> 5;
    const int y0   = (rblk & 31) << 1;
    const int n0   = nblk * BN;

    const int tid   = threadIdx.x;
    const int warp  = tid >> 5;
    const int lane  = tid & 31;
    const int warpM = warp & 3;             /* m base = warpM*32 */
    const int warpN = warp >> 2;            /* n base = warpN*64 */
    const int g     = lane >> 2;            /* groupID      */
    const int t     = lane & 3;             /* tid in group */
    const int ry    = warpM >> 1;           /* image row within block */
    const int xw0   = (warpM & 1) << 5;

    float acc[2][8][4];
#pragma unroll
    for (int mi = 0; mi < 2; mi++)
#pragma unroll
        for (int ni = 0; ni < 8; ni++)
#pragma unroll
            for (int r = 0; r < 4; r++) acc[mi][ni][r] = 0.f;

    const float* xs_b = g_xs + (size_t)b * HW * HW * CIN;

    for (int ci0 = 0; ci0 < CIN; ci0 += BKC) {
        __syncthreads();
        /* load x tile: 4 rows x 66 xp x 16 c */
        for (int i = tid; i < 4 * XPW * (BKC / 4); i += 256) {
            int cg  = i & 3;
            int q   = i >> 2;
            int row = q / XPW;
            int xp  = q - row * XPW;
            int yy  = y0 + row - 1;
            int xx  = xp - 1;
            float4 v = make_float4(0.f, 0.f, 0.f, 0.f);
            if ((unsigned)yy < HW && (unsigned)xx < HW)
                v = *(const float4*)(xs_b + ((yy * HW + xx) * CIN + ci0 + cg * 4));
            *(float4*)(xsm + (row * XPW + xp) * CP + cg * 4) = v;
        }
        for (int kk = 0; kk < 9; kk++) {
            __syncthreads();
            /* load W tap chunk: 16 c x 128 n */
            for (int i = tid; i < BKC * (BN / 4); i += 256) {
                int cog = i & 31;
                int c   = i >> 5;
                float4 v = *(const float4*)(g_wt + kk * CIN * COUT +
                                            (ci0 + c) * COUT + n0 + cog * 4);
                *(float4*)(wsm + c * WP + cog * 4) = v;
            }
            __syncthreads();

            const int dy = kk / 3;
            const int dx = kk - dy * 3;
            const float* xr = xsm + (ry + dy) * XPW * CP;

#pragma unroll
            for (int k8 = 0; k8 < BKC / 8; k8++) {
                const int k = k8 * 8 + t;
                uint32_t a[2][4];
#pragma unroll
                for (int mi = 0; mi < 2; mi++) {
                    int p = xw0 + mi * 16 + g + dx;
                    a[mi][0] = __float_as_uint(xr[p * CP + k]);
                    a[mi][1] = __float_as_uint(xr[(p + 8) * CP + k]);
                    a[mi][2] = __float_as_uint(xr[p * CP + k + 4]);
                    a[mi][3] = __float_as_uint(xr[(p + 8) * CP + k + 4]);
                }
                uint32_t bb[8][2];
#pragma unroll
                for (int ni = 0; ni < 8; ni++) {
                    int n = warpN * 64 + ni * 8 + g;
                    bb[ni][0] = __float_as_uint(wsm[k * WP + n]);
                    bb[ni][1] = __float_as_uint(wsm[(k + 4) * WP + n]);
                }
#pragma unroll
                for (int mi = 0; mi < 2; mi++)
#pragma unroll
                    for (int ni = 0; ni < 8; ni++)
                        mma_tf32(acc[mi][ni], a[mi], bb[ni]);
            }
        }
    }

    /* epilogue: out = acc * d[b,co] + bias */
    const float* dp = g_d + b * COUT;
    const int yy = y0 + ry;
#pragma unroll
    for (int mi = 0; mi < 2; mi++) {
        int x0p = xw0 + mi * 16 + g;
        float* o0 = out + ((size_t)(b * HW + yy) * HW + x0p) * COUT + n0;
        float* o1 = o0 + 8 * COUT;
#pragma unroll
        for (int ni = 0; ni < 8; ni++) {
            int n   = warpN * 64 + ni * 8 + t * 2;
            float d0  = dp[n0 + n],   d1  = dp[n0 + n + 1];
            float bb0 = bias[n0 + n], bb1 = bias[n0 + n + 1];
            float2 r0 = make_float2(acc[mi][ni][0] * d0 + bb0,
                                    acc[mi][ni][1] * d1 + bb1);
            float2 r1 = make_float2(acc[mi][ni][2] * d0 + bb0,
                                    acc[mi][ni][3] * d1 + bb1);
            *(float2*)(o0 + n) = r0;
            *(float2*)(o1 + n) = r1;
        }
    }
}

/* ------------------------------------------------------------------ */
extern "C" void kernel_launch(void* const* d_in, const int* in_sizes, int n_in,
                              void* d_out, int out_size) {
    (void)in_sizes; (void)n_in; (void)out_size;
    const float* x    = (const float*)d_in[0];
    const float* wl   = (const float*)d_in[1];
    const float* w    = (const float*)d_in[2];
    const float* bias = (const float*)d_in[3];
    const float* fcw  = (const float*)d_in[4];
    const float* fcb  = (const float*)d_in[5];
    float* out = (float*)d_out;

    style_kernel<<<NB, CIN>>>(wl, fcw, fcb);
    prepw_kernel<<<(KK * KK * CIN * COUT / 4) / 256, 256>>>(w);
    wsq_kernel<<<(CIN * COUT) / 256, 256>>>(w);
    modx_kernel<<<(NB * HW * HW * (CIN / 4)) / 256, 256>>>(x);
    demod_kernel<<<NB, COUT>>>();
    conv_kernel<<<dim3(4, 512), 256>>>(bias, out);
}

// round 4
// speedup vs baseline: 1.5710x; 1.5710x over previous
#include <cuda_runtime.h>
#include <cstdint>
#include <math.h>

#define CIN   512
#define COUT  512
#define WDIM  512
#define NB    16
#define HW    64
#define HWP   66

#define CONV_COEF 0.014731391274719739f   /* 1/sqrt(9*512) */
#define FC_COEF   0.044194173824159216f   /* 1/sqrt(512)   */

/* ------------------------------------------------------------------ */
/* scratch (__device__ globals; no cudaMalloc allowed)                 */
/* ------------------------------------------------------------------ */
__device__ float g_xsp[(size_t)NB * HWP * HWP * CIN];   /* padded x*s, k-pair-permuted */
__device__ float g_wpk[(size_t)9 * 2 * 64 * 2048];      /* W packed to B-fragment order */
__device__ float g_s[NB * CIN];
__device__ float g_d[NB * COUT];
__device__ float g_wsq[CIN * COUT];

__device__ __forceinline__ float tf32r(float x) {
    uint32_t u;
    asm("cvt.rna.tf32.f32 %0, %1;" : "=r"(u) : "f"(x));
    return __uint_as_float(u);
}
__device__ __forceinline__ uint32_t su32(const void* p) {
    uint32_t a;
    asm("{ .reg .u64 t; cvta.to.shared.u64 t, %1; cvt.u32.u64 %0, t; }" : "=r"(a) : "l"(p));
    return a;
}
__device__ __forceinline__ void cp16(uint32_t dst, const float* src) {
    asm volatile("cp.async.cg.shared.global [%0], [%1], 16;" :: "r"(dst), "l"(src));
}
__device__ __forceinline__ void cp_commit() { asm volatile("cp.async.commit_group;" ::: "memory"); }
template <int N> __device__ __forceinline__ void cp_wait() {
    asm volatile("cp.async.wait_group %0;" :: "n"(N) : "memory");
}

/* m16n8k8 tf32 mma: a-regs {A0.x,A1.x,A0.y,A1.y} = rows (g,g+8) x cols (t,t+4) */
__device__ __forceinline__ void mma8(float* c, float2 a0, float2 a1, float b0, float b1) {
    asm("mma.sync.aligned.m16n8k8.row.col.f32.tf32.tf32.f32 "
        "{%0,%1,%2,%3},{%4,%5,%6,%7},{%8,%9},{%0,%1,%2,%3};"
        : "+f"(c[0]), "+f"(c[1]), "+f"(c[2]), "+f"(c[3])
        : "r"(__float_as_uint(a0.x)), "r"(__float_as_uint(a1.x)),
          "r"(__float_as_uint(a0.y)), "r"(__float_as_uint(a1.y)),
          "r"(__float_as_uint(b0)), "r"(__float_as_uint(b1)));
}

/* ------------------------------------------------------------------ */
/* prep kernels                                                        */
/* ------------------------------------------------------------------ */
__global__ void style_kernel(const float* __restrict__ wl,
                             const float* __restrict__ fcw,
                             const float* __restrict__ fcb) {
    int b = blockIdx.x;
    int i = threadIdx.x;
    float acc = 0.f;
    for (int j = 0; j < WDIM; j++)
        acc = fmaf(wl[b * WDIM + j], fcw[j * CIN + i], acc);
    g_s[b * CIN + i] = acc * FC_COEF + fcb[i] + 1.0f;
}

/* padded, modulated, tf32-rounded x with within-8 k-permutation
   slots per 8-group: {k0,k4,k1,k5,k2,k6,k3,k7}  */
__global__ void xperm_kernel(const float* __restrict__ x) {
    int idx = blockIdx.x * 256 + threadIdx.x;       /* one 8-group */
    int c8 = idx & 63;
    int p  = idx >> 6;
    int px = p % HWP;
    int t2 = p / HWP;
    int py = t2 % HWP;
    int b  = t2 / HWP;
    int ci = c8 * 8;
    float4 lo = make_float4(0.f, 0.f, 0.f, 0.f), hi = lo;
    int ix = px - 1, iy = py - 1;
    if ((unsigned)ix < HW && (unsigned)iy < HW) {
        const float* xp = x + (((size_t)(b * HW + iy) * HW + ix) * CIN + ci);
        const float* sp = g_s + b * CIN + ci;
        lo = *(const float4*)xp;
        hi = *(const float4*)(xp + 4);
        lo.x = tf32r(lo.x * sp[0]); lo.y = tf32r(lo.y * sp[1]);
        lo.z = tf32r(lo.z * sp[2]); lo.w = tf32r(lo.w * sp[3]);
        hi.x = tf32r(hi.x * sp[4]); hi.y = tf32r(hi.y * sp[5]);
        hi.z = tf32r(hi.z * sp[6]); hi.w = tf32r(hi.w * sp[7]);
    }
    float* op = g_xsp + (((size_t)(b * HWP + py) * HWP + px) * CIN + ci);
    ((float4*)op)[0] = make_float4(lo.x, hi.x, lo.y, hi.y);
    ((float4*)op)[1] = make_float4(lo.z, hi.z, lo.w, hi.w);
}

/* pack W into exact B-fragment order:
   float4[idx], idx = ((((tap*2+nb)*64+kb)*4+wN)*4+q)*32 + lane
   components: {W(k,n), W(k+4,n), W(k,n+8), W(k+4,n+8)} * coef, tf32 */
__global__ void wpack_kernel(const float* __restrict__ w) {
    int idx = blockIdx.x * 256 + threadIdx.x;       /* float4 id, total 589824 */
    int lane = idx & 31;
    int r = idx >> 5;
    int q  = r & 3;  r >>= 2;
    int wN = r & 3;  r >>= 2;
    int kb = r & 63; r >>= 6;
    int nb = r & 1;
    int tap = r >> 1;
    int n = nb * 256 + wN * 64 + q * 16 + (lane >> 2);
    int k = kb * 8 + (lane & 3);
    const float* wp = w + (size_t)tap * CIN * COUT;
    float4 v;
    v.x = tf32r(wp[(size_t)k * COUT + n] * CONV_COEF);
    v.y = tf32r(wp[(size_t)(k + 4) * COUT + n] * CONV_COEF);
    v.z = tf32r(wp[(size_t)k * COUT + n + 8] * CONV_COEF);
    v.w = tf32r(wp[(size_t)(k + 4) * COUT + n + 8] * CONV_COEF);
    ((float4*)g_wpk)[idx] = v;
}

__global__ void wsq_kernel(const float* __restrict__ w) {
    int idx = blockIdx.x * 256 + threadIdx.x;
    float acc = 0.f;
#pragma unroll
    for (int t9 = 0; t9 < 9; t9++) {
        float v = w[(size_t)t9 * CIN * COUT + idx];
        acc = fmaf(v, v, acc);
    }
    g_wsq[idx] = acc;
}

__global__ void demod_kernel() {
    int b = blockIdx.x;
    int co = threadIdx.x;
    float acc = 0.f;
    for (int ci = 0; ci < CIN; ci++) {
        float s = g_s[b * CIN + ci];
        acc = fmaf(s * s, g_wsq[ci * COUT + co], acc);
    }
    g_d[b * COUT + co] = rsqrtf(acc * CONV_COEF * CONV_COEF + 1e-8f);
}

/* ------------------------------------------------------------------ */
/* pipelined tf32 mma.sync conv: CTA 128x256, warp 64x64               */
/* ------------------------------------------------------------------ */
#define XW   160                 /* bytes per pos (32 data words + 8 pad) */
#define XROW (HWP * XW)          /* 10560 */
#define XBUF (4 * XROW)          /* 42240 per chunk buffer */
#define BSTG 32768
#define SM_B0 (2 * XBUF)         /* 84480 */
#define SMEMSZ (2 * XBUF + 3 * BSTG)   /* 182784 */

__device__ __forceinline__ void load_x(uint32_t dst, const float* xb, int chunk,
                                       int y0, int tid) {
#pragma unroll
    for (int j = 0; j < 9; j++) {
        int i = tid + j * 256;
        if (i < 2112) {                       /* 4 rows x 66 pos x 8 cp16 */
            int q   = i & 7;
            int p   = i >> 3;
            int row = p / 66;
            int pos = p - row * 66;
            const float* src = xb + ((size_t)(y0 + row) * HWP + pos) * CIN + chunk * 32 + q * 4;
            cp16(dst + row * XROW + pos * XW + q * 16, src);
        }
    }
}

__device__ __forceinline__ void load_B(uint32_t dst, int tap, int nb, int chunk, int tid) {
    const float* src = g_wpk + ((size_t)((tap * 2 + nb) * 64 + chunk * 4)) * 2048;
#pragma unroll
    for (int j = 0; j < 8; j++) {
        int i = tid + j * 256;
        cp16(dst + i * 16, src + i * 4);
    }
}

__global__ __launch_bounds__(256, 1)
void conv_kernel(const float* __restrict__ bias, float* __restrict__ out) {
    extern __shared__ char sm[];
    __shared__ float s_d[256], s_bb[256];

    const int tid  = threadIdx.x;
    const int warp = tid >> 5;
    const int lane = tid & 31;
    const int g = lane >> 2, t = lane & 3;
    const int warpM = warp & 1;             /* output row within pair */
    const int warpN = warp >> 1;            /* 64-col block 0..3      */
    const int n0 = blockIdx.x * 256;
    const int gy = blockIdx.y;
    const int b  = gy >> 5;
    const int y0 = (gy & 31) * 2;

    s_d[tid]  = g_d[b * COUT + n0 + tid];
    s_bb[tid] = bias[n0 + tid];

    const uint32_t smx = su32(sm);
    const uint32_t smb = smx + SM_B0;
    const float* xb = g_xsp + (size_t)b * HWP * HWP * CIN;
    const int nbid = blockIdx.x;

    float acc[4][8][4];
#pragma unroll
    for (int mi = 0; mi < 4; mi++)
#pragma unroll
        for (int ni = 0; ni < 8; ni++)
#pragma unroll
            for (int r = 0; r < 4; r++) acc[mi][ni][r] = 0.f;

    /* prologue: x chunk0 + B stage0 | B stage1 */
    load_x(smx, xb, 0, y0, tid);
    load_B(smb, 0, nbid, 0, tid);
    cp_commit();
    load_B(smb + BSTG, 1, nbid, 0, tid);
    cp_commit();

    int chunk = 0, tap = 0;
    for (int s = 0; s < 144; s++) {
        if (s) __syncthreads();             /* all warps done with stage s-1 */
        const int s2 = s + 2;
        if (s2 < 144) {
            int c2 = s2 / 9;
            int t2 = s2 - 9 * c2;
            if (tap == 0 && chunk < 15)
                load_x(smx + ((chunk + 1) & 1) * XBUF, xb, chunk + 1, y0, tid);
            load_B(smb + (s2 % 3) * BSTG, t2, nbid, c2, tid);
            cp_commit();
            cp_wait<2>();                   /* stage s group complete */
        } else if (s2 == 144) {
            cp_wait<1>();
        } else {
            cp_wait<0>();
        }
        __syncthreads();

        const int dy = tap / 3;
        const int dx = tap - 3 * dy;
        const char* xrow = sm + (chunk & 1) * XBUF + (warpM + dy) * XROW;
        const char* bbas = sm + SM_B0 + (s % 3) * BSTG + warpN * 2048 + lane * 16;

#pragma unroll
        for (int k8 = 0; k8 < 4; k8++) {
            float4 Bf[4];
#pragma unroll
            for (int q = 0; q < 4; q++)
                Bf[q] = *(const float4*)(bbas + k8 * 8192 + q * 512);
            float2 A0[4], A1[4];
#pragma unroll
            for (int mi = 0; mi < 4; mi++) {
                const char* ap = xrow + (mi * 16 + g + dx) * XW + k8 * 32 + t * 8;
                A0[mi] = *(const float2*)ap;
                A1[mi] = *(const float2*)(ap + 8 * XW);
            }
#pragma unroll
            for (int mi = 0; mi < 4; mi++)
#pragma unroll
                for (int ni = 0; ni < 8; ni++) {
                    float b0 = (ni & 1) ? Bf[ni >> 1].z : Bf[ni >> 1].x;
                    float b1 = (ni & 1) ? Bf[ni >> 1].w : Bf[ni >> 1].y;
                    mma8(acc[mi][ni], A0[mi], A1[mi], b0, b1);
                }
        }
        if (++tap == 9) { tap = 0; chunk++; }
    }

    /* epilogue: out = acc * d + bias */
    const int y = y0 + warpM;
    float* obase = out + ((size_t)(b * HW + y) * HW) * COUT + n0;
#pragma unroll
    for (int mi = 0; mi < 4; mi++) {
        int px0 = mi * 16 + g;
        float* o0 = obase + (size_t)px0 * COUT;
        float* o1 = obase + (size_t)(px0 + 8) * COUT;
#pragma unroll
        for (int ni = 0; ni < 8; ni++) {
            int ln = warpN * 64 + ni * 8 + t * 2;
            float d0 = s_d[ln],  d1 = s_d[ln + 1];
            float c0 = s_bb[ln], c1 = s_bb[ln + 1];
            *(float2*)(o0 + ln) = make_float2(acc[mi][ni][0] * d0 + c0,
                                              acc[mi][ni][1] * d1 + c1);
            *(float2*)(o1 + ln) = make_float2(acc[mi][ni][2] * d0 + c0,
                                              acc[mi][ni][3] * d1 + c1);
        }
    }
}

/* ------------------------------------------------------------------ */
extern "C" void kernel_launch(void* const* d_in, const int* in_sizes, int n_in,
                              void* d_out, int out_size) {
    (void)in_sizes; (void)n_in; (void)out_size;
    const float* x    = (const float*)d_in[0];
    const float* wl   = (const float*)d_in[1];
    const float* w    = (const float*)d_in[2];
    const float* bias = (const float*)d_in[3];
    const float* fcw  = (const float*)d_in[4];
    const float* fcb  = (const float*)d_in[5];
    float* out = (float*)d_out;

    style_kernel<<<NB, CIN>>>(wl, fcw, fcb);
    xperm_kernel<<<(NB * HWP * HWP * 64) / 256, 256>>>(x);
    wpack_kernel<<<2304, 256>>>(w);   /* 589824 float4 / 256 */
    wsq_kernel<<<(CIN * COUT) / 256, 256>>>(w);
    demod_kernel<<<NB, COUT>>>();

    cudaFuncSetAttribute(conv_kernel, cudaFuncAttributeMaxDynamicSharedMemorySize, SMEMSZ);
    conv_kernel<<<dim3(2, 512), 256, SMEMSZ>>>(bias, out);
}

// round 5
// speedup vs baseline: 2.4965x; 1.5891x over previous
#include <cuda_runtime.h>
#include <cuda_fp16.h>
#include <cstdint>
#include <math.h>

#define CIN   512
#define COUT  512
#define WDIM  512
#define NB    16
#define HW    64
#define HWP   66

#define CONV_COEF 0.014731391274719739f   /* 1/sqrt(9*512) */
#define FC_COEF   0.044194173824159216f   /* 1/sqrt(512)   */

/* ------------------------------------------------------------------ */
/* scratch (__device__ globals)                                        */
/* ------------------------------------------------------------------ */
/* padded modulated x, fp16, chunk-major: [b][ck 32][py 66][px 66][32ch]
   within each 16-ch (k16) group words permuted {p0,p4,p1,p5,p2,p6,p3,p7} */
__device__ __half g_xsp[(size_t)NB * 32 * HWP * HWP * 32];
/* W packed fp16 to B-fragment order:
   uint4[idx], idx = ((((tap*2+nb)*32+kg)*4+wN)*4+q)*32+lane */
__device__ __half g_wpk[(size_t)9 * 512 * 512];
__device__ float g_s[NB * CIN];
__device__ float g_d[NB * COUT];
__device__ float g_wsq[CIN * COUT];

__device__ __forceinline__ uint32_t su32(const void* p) {
    uint32_t a;
    asm("{ .reg .u64 t; cvta.to.shared.u64 t, %1; cvt.u32.u64 %0, t; }" : "=r"(a) : "l"(p));
    return a;
}
__device__ __forceinline__ void cp16(uint32_t dst, const void* src) {
    asm volatile("cp.async.cg.shared.global [%0], [%1], 16;" :: "r"(dst), "l"(src));
}
__device__ __forceinline__ void cp_commit() { asm volatile("cp.async.commit_group;" ::: "memory"); }
template <int N> __device__ __forceinline__ void cp_wait() {
    asm volatile("cp.async.wait_group %0;" :: "n"(N) : "memory");
}
__device__ __forceinline__ uint32_t h2u(__half2 h) { return *(uint32_t*)&h; }

/* m16n8k16 f16 mma, fp32 accum */
__device__ __forceinline__ void mma16(float* c, uint32_t a0, uint32_t a1,
                                      uint32_t a2, uint32_t a3,
                                      uint32_t b0, uint32_t b1) {
    asm("mma.sync.aligned.m16n8k16.row.col.f32.f16.f16.f32 "
        "{%0,%1,%2,%3},{%4,%5,%6,%7},{%8,%9},{%0,%1,%2,%3};"
        : "+f"(c[0]), "+f"(c[1]), "+f"(c[2]), "+f"(c[3])
        : "r"(a0), "r"(a1), "r"(a2), "r"(a3), "r"(b0), "r"(b1));
}

/* ------------------------------------------------------------------ */
/* prep kernels                                                        */
/* ------------------------------------------------------------------ */
__global__ void style_kernel(const float* __restrict__ wl,
                             const float* __restrict__ fcw,
                             const float* __restrict__ fcb) {
    int b = blockIdx.x;
    int i = threadIdx.x;
    float acc = 0.f;
    for (int j = 0; j < WDIM; j++)
        acc = fmaf(wl[b * WDIM + j], fcw[j * CIN + i], acc);
    g_s[b * CIN + i] = acc * FC_COEF + fcb[i] + 1.0f;
}

/* padded modulated fp16 x: one thread = one 16-ch group at one pos.
   out words permuted {0,4,1,5,2,6,3,7} (pj = half2(c2j, c2j+1)) */
__global__ void xperm_kernel(const float* __restrict__ x) {
    int idx = blockIdx.x * 256 + threadIdx.x;     /* total 4,460,544 */
    int grp = idx & 1;
    int r   = idx >> 1;
    int px  = r % HWP;  r /= HWP;
    int py  = r % HWP;  r /= HWP;
    int ck  = r & 31;
    int b   = r >> 5;
    int ci  = ck * 32 + grp * 16;
    float v[16];
#pragma unroll
    for (int j = 0; j < 16; j++) v[j] = 0.f;
    int ix = px - 1, iy = py - 1;
    if ((unsigned)ix < HW && (unsigned)iy < HW) {
        const float* xp = x + (((size_t)(b * HW + iy) * HW + ix) * CIN + ci);
        const float* sp = g_s + b * CIN + ci;
#pragma unroll
        for (int j = 0; j < 16; j++) v[j] = xp[j] * sp[j];
    }
    uint32_t w[8];
#pragma unroll
    for (int j = 0; j < 8; j++)
        w[j] = h2u(__floats2half2_rn(v[2 * j], v[2 * j + 1]));
    uint4 o0 = make_uint4(w[0], w[4], w[1], w[5]);
    uint4 o1 = make_uint4(w[2], w[6], w[3], w[7]);
    uint4* op = (uint4*)(g_xsp + ((((size_t)(b * 32 + ck) * HWP + py) * HWP + px) * 32 + grp * 16));
    op[0] = o0;
    op[1] = o1;
}

/* pack W fp16 into exact m16n8k16 B-fragment order */
__global__ void wpack_kernel(const float* __restrict__ w) {
    int idx = blockIdx.x * 256 + threadIdx.x;     /* uint4 id, total 294912 */
    int lane = idx & 31;
    int r = idx >> 5;
    int q  = r & 3;  r >>= 2;
    int wN = r & 3;  r >>= 2;
    int kg = r & 31; r >>= 5;
    int nb = r & 1;
    int tap = r >> 1;
    int t = lane & 3, g = lane >> 2;
    int n  = nb * 256 + wN * 64 + q * 16 + g;
    int k0 = kg * 16 + 2 * t;
    const float* wp = w + (size_t)tap * CIN * COUT;
    uint4 o;
    o.x = h2u(__floats2half2_rn(wp[(size_t)k0 * COUT + n] * CONV_COEF,
                                wp[(size_t)(k0 + 1) * COUT + n] * CONV_COEF));
    o.y = h2u(__floats2half2_rn(wp[(size_t)(k0 + 8) * COUT + n] * CONV_COEF,
                                wp[(size_t)(k0 + 9) * COUT + n] * CONV_COEF));
    o.z = h2u(__floats2half2_rn(wp[(size_t)k0 * COUT + n + 8] * CONV_COEF,
                                wp[(size_t)(k0 + 1) * COUT + n + 8] * CONV_COEF));
    o.w = h2u(__floats2half2_rn(wp[(size_t)(k0 + 8) * COUT + n + 8] * CONV_COEF,
                                wp[(size_t)(k0 + 9) * COUT + n + 8] * CONV_COEF));
    ((uint4*)g_wpk)[idx] = o;
}

__global__ void wsq_kernel(const float* __restrict__ w) {
    int idx = blockIdx.x * 256 + threadIdx.x;
    float acc = 0.f;
#pragma unroll
    for (int t9 = 0; t9 < 9; t9++) {
        float v = w[(size_t)t9 * CIN * COUT + idx];
        acc = fmaf(v, v, acc);
    }
    g_wsq[idx] = acc;
}

__global__ void demod_kernel() {
    int b = blockIdx.x;
    int co = threadIdx.x;
    float acc = 0.f;
    for (int ci = 0; ci < CIN; ci++) {
        float s = g_s[b * CIN + ci];
        acc = fmaf(s * s, g_wsq[ci * COUT + co], acc);
    }
    g_d[b * COUT + co] = rsqrtf(acc * CONV_COEF * CONV_COEF + 1e-8f);
}

/* ------------------------------------------------------------------ */
/* pipelined fp16 mma.sync conv: CTA 128x256, warp 64x64               */
/* ------------------------------------------------------------------ */
#define XW    96                  /* bytes/pos: 64B data + 32B pad (24w ≡ 24 mod 32) */
#define XROW  (HWP * XW)          /* 6336 */
#define XBUF  (4 * XROW)          /* 25344 */
#define BSTG  16384
#define SM_B0 (2 * XBUF)          /* 50688 */
#define SMEMSZ (2 * XBUF + 4 * BSTG)   /* 116224 */
#define NSTG  144

__device__ __forceinline__ void load_x(uint32_t dst, int b, int ck, int y0, int tid) {
    const char* xb = (const char*)g_xsp + ((size_t)(b * 32 + ck) * HWP * HWP) * 64;
#pragma unroll
    for (int j = 0; j < 5; j++) {
        int i = tid + j * 256;
        if (i < 1056) {                    /* 4 rows x 66 pos x 4 cp16 */
            int q   = i & 3;
            int p   = i >> 2;
            int row = p / 66;
            int pos = p - row * 66;
            const char* src = xb + ((size_t)(y0 + row) * HWP + pos) * 64 + q * 16;
            cp16(dst + row * XROW + pos * XW + q * 16, src);
        }
    }
}

__device__ __forceinline__ void load_B(uint32_t dst, int tap, int nb, int chunk, int tid) {
    const char* src = (const char*)g_wpk + ((size_t)((tap * 2 + nb) * 32 + chunk * 2)) * 8192;
#pragma unroll
    for (int j = 0; j < 4; j++) {
        int i = tid + j * 256;
        cp16(dst + i * 16, src + i * 16);
    }
}

__global__ __launch_bounds__(256, 1)
void conv_kernel(const float* __restrict__ bias, float* __restrict__ out) {
    extern __shared__ char sm[];
    __shared__ float s_d[256], s_bb[256];

    const int tid  = threadIdx.x;
    const int warp = tid >> 5;
    const int lane = tid & 31;
    const int g = lane >> 2, t = lane & 3;
    const int warpM = warp & 1;
    const int warpN = warp >> 1;
    const int nbid = blockIdx.x;
    const int n0 = nbid * 256;
    const int gy = blockIdx.y;
    const int b  = gy >> 5;
    const int y0 = (gy & 31) * 2;          /* padded row base */

    s_d[tid]  = g_d[b * COUT + n0 + tid];
    s_bb[tid] = bias[n0 + tid];

    const uint32_t smx = su32(sm);
    const uint32_t smb = smx + SM_B0;

    float acc[4][8][4];
#pragma unroll
    for (int mi = 0; mi < 4; mi++)
#pragma unroll
        for (int ni = 0; ni < 8; ni++)
#pragma unroll
            for (int r = 0; r < 4; r++) acc[mi][ni][r] = 0.f;

    /* prologue: x(ck0)+B(s0) | B(s1) | B(s2) */
    load_x(smx, b, 0, y0, tid);
    load_B(smb, 0, nbid, 0, tid);
    cp_commit();
    load_B(smb + BSTG, 1, nbid, 0, tid);
    cp_commit();
    load_B(smb + 2 * BSTG, 2, nbid, 0, tid);
    cp_commit();

    int chunk = 0, tap = 0;
    for (int s = 0; s < NSTG; s++) {
        if (s) __syncthreads();
        const int s3 = s + 3;
        if (s3 < NSTG) {
            int c3 = s3 / 9;
            int t3 = s3 - 9 * c3;
            if (tap == 0 && chunk < 15)
                load_x(smx + ((chunk + 1) & 1) * XBUF, b, chunk + 1, y0, tid);
            load_B(smb + (s3 & 3) * BSTG, t3, nbid, c3, tid);
            cp_commit();
            cp_wait<3>();
        } else if (s3 == NSTG) {
            cp_wait<2>();
        } else if (s3 == NSTG + 1) {
            cp_wait<1>();
        } else {
            cp_wait<0>();
        }
        __syncthreads();

        const int dy = tap / 3;
        const int dx = tap - 3 * dy;
        const char* xrow = sm + (chunk & 1) * XBUF + (warpM + dy) * XROW;
        const char* bbas = sm + SM_B0 + (s & 3) * BSTG + warpN * 2048 + lane * 16;

#pragma unroll
        for (int kg = 0; kg < 2; kg++) {
            float4 Bf[4];
#pragma unroll
            for (int q = 0; q < 4; q++)
                Bf[q] = *(const float4*)(bbas + kg * 8192 + q * 512);
            float2 A0[4], A1[4];
#pragma unroll
            for (int mi = 0; mi < 4; mi++) {
                const char* ap = xrow + (mi * 16 + g + dx) * XW + kg * 32 + t * 8;
                A0[mi] = *(const float2*)ap;
                A1[mi] = *(const float2*)(ap + 8 * XW);
            }
#pragma unroll
            for (int mi = 0; mi < 4; mi++)
#pragma unroll
                for (int ni = 0; ni < 8; ni++) {
                    uint32_t b0 = __float_as_uint((ni & 1) ? Bf[ni >> 1].z : Bf[ni >> 1].x);
                    uint32_t b1 = __float_as_uint((ni & 1) ? Bf[ni >> 1].w : Bf[ni >> 1].y);
                    mma16(acc[mi][ni],
                          __float_as_uint(A0[mi].x), __float_as_uint(A1[mi].x),
                          __float_as_uint(A0[mi].y), __float_as_uint(A1[mi].y),
                          b0, b1);
                }
        }
        if (++tap == 9) { tap = 0; chunk++; }
    }

    /* epilogue: out = acc * d + bias */
    const int y = y0 + warpM;
    float* obase = out + ((size_t)(b * HW + y) * HW) * COUT + n0;
#pragma unroll
    for (int mi = 0; mi < 4; mi++) {
        int px0 = mi * 16 + g;
        float* o0 = obase + (size_t)px0 * COUT;
        float* o1 = obase + (size_t)(px0 + 8) * COUT;
#pragma unroll
        for (int ni = 0; ni < 8; ni++) {
            int ln = warpN * 64 + ni * 8 + t * 2;
            float d0 = s_d[ln],  d1 = s_d[ln + 1];
            float c0 = s_bb[ln], c1 = s_bb[ln + 1];
            *(float2*)(o0 + ln) = make_float2(acc[mi][ni][0] * d0 + c0,
                                              acc[mi][ni][1] * d1 + c1);
            *(float2*)(o1 + ln) = make_float2(acc[mi][ni][2] * d0 + c0,
                                              acc[mi][ni][3] * d1 + c1);
        }
    }
}

/* ------------------------------------------------------------------ */
extern "C" void kernel_launch(void* const* d_in, const int* in_sizes, int n_in,
                              void* d_out, int out_size) {
    (void)in_sizes; (void)n_in; (void)out_size;
    const float* x    = (const float*)d_in[0];
    const float* wl   = (const float*)d_in[1];
    const float* w    = (const float*)d_in[2];
    const float* bias = (const float*)d_in[3];
    const float* fcw  = (const float*)d_in[4];
    const float* fcb  = (const float*)d_in[5];
    float* out = (float*)d_out;

    style_kernel<<<NB, CIN>>>(wl, fcw, fcb);
    xperm_kernel<<<17424, 256>>>(x);      /* 16*32*66*66*2 / 256 */
    wpack_kernel<<<1152, 256>>>(w);       /* 294912 / 256 */
    wsq_kernel<<<(CIN * COUT) / 256, 256>>>(w);
    demod_kernel<<<NB, COUT>>>();

    cudaFuncSetAttribute(conv_kernel, cudaFuncAttributeMaxDynamicSharedMemorySize, SMEMSZ);
    conv_kernel<<<dim3(2, 512), 256, SMEMSZ>>>(bias, out);
}

// round 6
// speedup vs baseline: 2.6934x; 1.0789x over previous
#include <cuda_runtime.h>
#include <cuda_fp16.h>
#include <cstdint>
#include <math.h>

#define CIN   512
#define COUT  512
#define WDIM  512
#define NB    16
#define HW    64
#define HWP   66

#define CONV_COEF 0.014731391274719739f   /* 1/sqrt(9*512) */
#define FC_COEF   0.044194173824159216f   /* 1/sqrt(512)   */

/* ------------------------------------------------------------------ */
/* scratch (__device__ globals)                                        */
/* ------------------------------------------------------------------ */
/* padded modulated x, fp16, chunk-major: [b][ck 32][py 66][px 66][32ch]
   within each 16-ch (k16) group words permuted {p0,p4,p1,p5,p2,p6,p3,p7} */
__device__ __half g_xsp[(size_t)NB * 32 * HWP * HWP * 32];
/* W packed fp16 to B-fragment order:
   uint4[idx], idx = ((((tap*2+nb)*32+kg)*4+wN)*4+q)*32+lane */
__device__ __half g_wpk[(size_t)9 * 512 * 512];
__device__ float g_s[NB * CIN];
__device__ float g_d[NB * COUT];
__device__ float g_wsq[CIN * COUT];

__device__ __forceinline__ uint32_t su32(const void* p) {
    uint32_t a;
    asm("{ .reg .u64 t; cvta.to.shared.u64 t, %1; cvt.u32.u64 %0, t; }" : "=r"(a) : "l"(p));
    return a;
}
__device__ __forceinline__ void cp16(uint32_t dst, const void* src) {
    asm volatile("cp.async.cg.shared.global [%0], [%1], 16;" :: "r"(dst), "l"(src));
}
__device__ __forceinline__ void cp_commit() { asm volatile("cp.async.commit_group;" ::: "memory"); }
template <int N> __device__ __forceinline__ void cp_wait() {
    asm volatile("cp.async.wait_group %0;" :: "n"(N) : "memory");
}
__device__ __forceinline__ uint32_t h2u(__half2 h) { return *(uint32_t*)&h; }

/* m16n8k16 f16 mma, fp32 accum */
__device__ __forceinline__ void mma16(float* c, uint32_t a0, uint32_t a1,
                                      uint32_t a2, uint32_t a3,
                                      uint32_t b0, uint32_t b1) {
    asm("mma.sync.aligned.m16n8k16.row.col.f32.f16.f16.f32 "
        "{%0,%1,%2,%3},{%4,%5,%6,%7},{%8,%9},{%0,%1,%2,%3};"
        : "+f"(c[0]), "+f"(c[1]), "+f"(c[2]), "+f"(c[3])
        : "r"(a0), "r"(a1), "r"(a2), "r"(a3), "r"(b0), "r"(b1));
}

/* ------------------------------------------------------------------ */
/* prep kernels                                                        */
/* ------------------------------------------------------------------ */
__global__ void style_kernel(const float* __restrict__ wl,
                             const float* __restrict__ fcw,
                             const float* __restrict__ fcb) {
    int b = blockIdx.x;
    int i = threadIdx.x;
    float acc = 0.f;
    for (int j = 0; j < WDIM; j++)
        acc = fmaf(wl[b * WDIM + j], fcw[j * CIN + i], acc);
    g_s[b * CIN + i] = acc * FC_COEF + fcb[i] + 1.0f;
}

/* padded modulated fp16 x: one thread = one 16-ch group at one pos. */
__global__ void xperm_kernel(const float* __restrict__ x) {
    int idx = blockIdx.x * 256 + threadIdx.x;     /* total 4,460,544 */
    int grp = idx & 1;
    int r   = idx >> 1;
    int px  = r % HWP;  r /= HWP;
    int py  = r % HWP;  r /= HWP;
    int ck  = r & 31;
    int b   = r >> 5;
    int ci  = ck * 32 + grp * 16;
    float v[16];
#pragma unroll
    for (int j = 0; j < 16; j++) v[j] = 0.f;
    int ix = px - 1, iy = py - 1;
    if ((unsigned)ix < HW && (unsigned)iy < HW) {
        const float* xp = x + (((size_t)(b * HW + iy) * HW + ix) * CIN + ci);
        const float* sp = g_s + b * CIN + ci;
#pragma unroll
        for (int j = 0; j < 16; j++) v[j] = xp[j] * sp[j];
    }
    uint32_t w[8];
#pragma unroll
    for (int j = 0; j < 8; j++)
        w[j] = h2u(__floats2half2_rn(v[2 * j], v[2 * j + 1]));
    uint4 o0 = make_uint4(w[0], w[4], w[1], w[5]);
    uint4 o1 = make_uint4(w[2], w[6], w[3], w[7]);
    uint4* op = (uint4*)(g_xsp + ((((size_t)(b * 32 + ck) * HWP + py) * HWP + px) * 32 + grp * 16));
    op[0] = o0;
    op[1] = o1;
}

/* pack W fp16 into exact m16n8k16 B-fragment order */
__global__ void wpack_kernel(const float* __restrict__ w) {
    int idx = blockIdx.x * 256 + threadIdx.x;     /* uint4 id, total 294912 */
    int lane = idx & 31;
    int r = idx >> 5;
    int q  = r & 3;  r >>= 2;
    int wN = r & 3;  r >>= 2;
    int kg = r & 31; r >>= 5;
    int nb = r & 1;
    int tap = r >> 1;
    int t = lane & 3, g = lane >> 2;
    int n  = nb * 256 + wN * 64 + q * 16 + g;
    int k0 = kg * 16 + 2 * t;
    const float* wp = w + (size_t)tap * CIN * COUT;
    uint4 o;
    o.x = h2u(__floats2half2_rn(wp[(size_t)k0 * COUT + n] * CONV_COEF,
                                wp[(size_t)(k0 + 1) * COUT + n] * CONV_COEF));
    o.y = h2u(__floats2half2_rn(wp[(size_t)(k0 + 8) * COUT + n] * CONV_COEF,
                                wp[(size_t)(k0 + 9) * COUT + n] * CONV_COEF));
    o.z = h2u(__floats2half2_rn(wp[(size_t)k0 * COUT + n + 8] * CONV_COEF,
                                wp[(size_t)(k0 + 1) * COUT + n + 8] * CONV_COEF));
    o.w = h2u(__floats2half2_rn(wp[(size_t)(k0 + 8) * COUT + n + 8] * CONV_COEF,
                                wp[(size_t)(k0 + 9) * COUT + n + 8] * CONV_COEF));
    ((uint4*)g_wpk)[idx] = o;
}

__global__ void wsq_kernel(const float* __restrict__ w) {
    int idx = blockIdx.x * 256 + threadIdx.x;
    float acc = 0.f;
#pragma unroll
    for (int t9 = 0; t9 < 9; t9++) {
        float v = w[(size_t)t9 * CIN * COUT + idx];
        acc = fmaf(v, v, acc);
    }
    g_wsq[idx] = acc;
}

__global__ void demod_kernel() {
    int b = blockIdx.x;
    int co = threadIdx.x;
    float acc = 0.f;
    for (int ci = 0; ci < CIN; ci++) {
        float s = g_s[b * CIN + ci];
        acc = fmaf(s * s, g_wsq[ci * COUT + co], acc);
    }
    g_d[b * COUT + co] = rsqrtf(acc * CONV_COEF * CONV_COEF + 1e-8f);
}

/* ------------------------------------------------------------------ */
/* pipelined fp16 mma.sync conv: CTA 128x256, warp 64x64               */
/* 48 stages (cin-chunk x kernel-row), 3 taps per stage                */
/* ------------------------------------------------------------------ */
#define XW    96                  /* bytes/pos: 64B data + 32B pad */
#define XROW  (HWP * XW)          /* 6336 */
#define XBUF  (4 * XROW)          /* 25344 */
#define BSTG  49152               /* 3 taps x 16 KB */
#define SM_B0 (2 * XBUF)          /* 50688 */
#define SMEMSZ (2 * XBUF + 3 * BSTG)   /* 198144 */
#define NSTG  48

__device__ __forceinline__ void load_x(uint32_t dst, int b, int ck, int y0, int tid) {
    const char* xb = (const char*)g_xsp + ((size_t)(b * 32 + ck) * HWP * HWP) * 64;
#pragma unroll
    for (int j = 0; j < 5; j++) {
        int i = tid + j * 256;
        if (i < 1056) {                    /* 4 rows x 66 pos x 4 cp16 */
            int q   = i & 3;
            int p   = i >> 2;
            int row = p / 66;
            int pos = p - row * 66;
            const char* src = xb + ((size_t)(y0 + row) * HWP + pos) * 64 + q * 16;
            cp16(dst + row * XROW + pos * XW + q * 16, src);
        }
    }
}

/* load 3 taps (kernel row trow) for one cin-chunk: 48 KB */
__device__ __forceinline__ void load_B(uint32_t dst, int trow, int nb, int chunk, int tid) {
    const char* wb = (const char*)g_wpk;
#pragma unroll
    for (int j = 0; j < 12; j++) {
        int i   = tid + j * 256;          /* 3072 x 16B */
        int tpi = i >> 10;                /* tap within row */
        int off = i & 1023;
        const char* src = wb + (size_t)(trow * 3 + tpi) * 524288
                             + (size_t)nb * 262144 + (size_t)chunk * 16384 + off * 16;
        cp16(dst + i * 16, src);
    }
}

__global__ __launch_bounds__(256, 1)
void conv_kernel(const float* __restrict__ bias, float* __restrict__ out) {
    extern __shared__ char sm[];
    __shared__ float s_d[256], s_bb[256];

    const int tid  = threadIdx.x;
    const int warp = tid >> 5;
    const int lane = tid & 31;
    const int g = lane >> 2, t = lane & 3;
    const int warpM = warp & 1;
    const int warpN = warp >> 1;
    const int nbid = blockIdx.x;
    const int n0 = nbid * 256;
    const int gy = blockIdx.y;
    const int b  = gy >> 5;
    const int y0 = (gy & 31) * 2;          /* padded row base */

    s_d[tid]  = g_d[b * COUT + n0 + tid];
    s_bb[tid] = bias[n0 + tid];

    const uint32_t smx = su32(sm);
    const uint32_t smb = smx + SM_B0;

    float acc[4][8][4];
#pragma unroll
    for (int mi = 0; mi < 4; mi++)
#pragma unroll
        for (int ni = 0; ni < 8; ni++)
#pragma unroll
            for (int r = 0; r < 4; r++) acc[mi][ni][r] = 0.f;

    /* prologue groups: G0 = x(ck0)+B(s0); G1 = B(s1) */
    load_x(smx, b, 0, y0, tid);
    load_B(smb, 0, nbid, 0, tid);
    cp_commit();
    load_B(smb + BSTG, 1, nbid, 0, tid);
    cp_commit();

    int chunk = 0, trow = 0;
    for (int s = 0; s < NSTG; s++) {
        /* this stage's data = group issued at s-2 (or prologue) */
        cp_wait<1>();
        __syncthreads();
        /* prefetch stage s+2 (buffer consumed at stage s-1: safe after sync) */
        const int s2 = s + 2;
        if (s2 < NSTG) {
            int c2 = s2 / 3;
            int r2 = s2 - 3 * c2;
            if (trow == 1 && chunk < 15)
                load_x(smx + ((chunk + 1) & 1) * XBUF, b, chunk + 1, y0, tid);
            load_B(smb + (s2 % 3) * BSTG, r2, nbid, c2, tid);
        }
        cp_commit();

        const char* xrow = sm + (chunk & 1) * XBUF + (warpM + trow) * XROW;
        const char* bst  = sm + SM_B0 + (s % 3) * BSTG + warpN * 2048 + lane * 16;

#pragma unroll
        for (int dx = 0; dx < 3; dx++) {
#pragma unroll
            for (int kg = 0; kg < 2; kg++) {
                const char* bbas = bst + dx * 16384 + kg * 8192;
                float4 Bf[4];
#pragma unroll
                for (int q = 0; q < 4; q++)
                    Bf[q] = *(const float4*)(bbas + q * 512);
                float2 A0[4], A1[4];
#pragma unroll
                for (int mi = 0; mi < 4; mi++) {
                    const char* ap = xrow + (mi * 16 + g + dx) * XW + kg * 32 + t * 8;
                    A0[mi] = *(const float2*)ap;
                    A1[mi] = *(const float2*)(ap + 8 * XW);
                }
#pragma unroll
                for (int mi = 0; mi < 4; mi++)
#pragma unroll
                    for (int ni = 0; ni < 8; ni++) {
                        uint32_t b0 = __float_as_uint((ni & 1) ? Bf[ni >> 1].z : Bf[ni >> 1].x);
                        uint32_t b1 = __float_as_uint((ni & 1) ? Bf[ni >> 1].w : Bf[ni >> 1].y);
                        mma16(acc[mi][ni],
                              __float_as_uint(A0[mi].x), __float_as_uint(A1[mi].x),
                              __float_as_uint(A0[mi].y), __float_as_uint(A1[mi].y),
                              b0, b1);
                    }
            }
        }
        if (++trow == 3) { trow = 0; chunk++; }
    }

    /* epilogue: out = acc * d + bias */
    const int y = y0 + warpM;
    float* obase = out + ((size_t)(b * HW + y) * HW) * COUT + n0;
#pragma unroll
    for (int mi = 0; mi < 4; mi++) {
        int px0 = mi * 16 + g;
        float* o0 = obase + (size_t)px0 * COUT;
        float* o1 = obase + (size_t)(px0 + 8) * COUT;
#pragma unroll
        for (int ni = 0; ni < 8; ni++) {
            int ln = warpN * 64 + ni * 8 + t * 2;
            float d0 = s_d[ln],  d1 = s_d[ln + 1];
            float c0 = s_bb[ln], c1 = s_bb[ln + 1];
            *(float2*)(o0 + ln) = make_float2(acc[mi][ni][0] * d0 + c0,
                                              acc[mi][ni][1] * d1 + c1);
            *(float2*)(o1 + ln) = make_float2(acc[mi][ni][2] * d0 + c0,
                                              acc[mi][ni][3] * d1 + c1);
        }
    }
}

/* ------------------------------------------------------------------ */
extern "C" void kernel_launch(void* const* d_in, const int* in_sizes, int n_in,
                              void* d_out, int out_size) {
    (void)in_sizes; (void)n_in; (void)out_size;
    const float* x    = (const float*)d_in[0];
    const float* wl   = (const float*)d_in[1];
    const float* w    = (const float*)d_in[2];
    const float* bias = (const float*)d_in[3];
    const float* fcw  = (const float*)d_in[4];
    const float* fcb  = (const float*)d_in[5];
    float* out = (float*)d_out;

    style_kernel<<<NB, CIN>>>(wl, fcw, fcb);
    xperm_kernel<<<17424, 256>>>(x);      /* 16*32*66*66*2 / 256 */
    wpack_kernel<<<1152, 256>>>(w);       /* 294912 / 256 */
    wsq_kernel<<<(CIN * COUT) / 256, 256>>>(w);
    demod_kernel<<<NB, COUT>>>();

    cudaFuncSetAttribute(conv_kernel, cudaFuncAttributeMaxDynamicSharedMemorySize, SMEMSZ);
    conv_kernel<<<dim3(2, 512), 256, SMEMSZ>>>(bias, out);
}

// round 8
// speedup vs baseline: 4.0828x; 1.5159x over previous
#include <cuda_runtime.h>
#include <cuda_fp16.h>
#include <cstdint>
#include <math.h>

#define CIN   512
#define COUT  512
#define WDIM  512
#define NB    16
#define HW    64

#define CONV_COEF 0.014731391274719739f   /* 1/sqrt(9*512) */
#define FC_COEF   0.044194173824159216f   /* 1/sqrt(512)   */

#define NTILE 16384                        /* 16 imgs x 32x32 tiles */

/* ------------------------------------------------------------------ */
/* scratch (__device__ globals)                                        */
/* ------------------------------------------------------------------ */
/* V: [pos 16][kc 32][mblk 1024][512B] fp16, fragment-interleaved      */
__device__ __half g_V[(size_t)16 * 32 * 1024 * 256];
/* U packed fp16 B-fragment order: [pos][nblk 4][ck 16] x 8KB          */
__device__ __half g_U[(size_t)16 * 512 * 512];
__device__ float  g_U32[(size_t)16 * 512 * 512];
/* GEMM out: [pos 16][m 16384][n 512] fp32                             */
__device__ float  g_M[(size_t)16 * NTILE * 512];
__device__ float  g_s[NB * CIN];
__device__ float  g_d[NB * COUT];
__device__ float  g_wsq[CIN * COUT];

__device__ __forceinline__ uint32_t su32(const void* p) {
    uint32_t a;
    asm("{ .reg .u64 t; cvta.to.shared.u64 t, %1; cvt.u32.u64 %0, t; }" : "=r"(a) : "l"(p));
    return a;
}
__device__ __forceinline__ void cp16(uint32_t dst, const void* src) {
    asm volatile("cp.async.cg.shared.global [%0], [%1], 16;" :: "r"(dst), "l"(src));
}
__device__ __forceinline__ void cp_commit() { asm volatile("cp.async.commit_group;" ::: "memory"); }
template <int N> __device__ __forceinline__ void cp_wait() {
    asm volatile("cp.async.wait_group %0;" :: "n"(N) : "memory");
}
__device__ __forceinline__ uint32_t h2u(__half2 h) { return *(uint32_t*)&h; }

__device__ __forceinline__ void mma16(float* c, uint32_t a0, uint32_t a1,
                                      uint32_t a2, uint32_t a3,
                                      uint32_t b0, uint32_t b1) {
    asm("mma.sync.aligned.m16n8k16.row.col.f32.f16.f16.f32 "
        "{%0,%1,%2,%3},{%4,%5,%6,%7},{%8,%9},{%0,%1,%2,%3};"
        : "+f"(c[0]), "+f"(c[1]), "+f"(c[2]), "+f"(c[3])
        : "r"(a0), "r"(a1), "r"(a2), "r"(a3), "r"(b0), "r"(b1));
}

/* ------------------------------------------------------------------ */
/* prep: style, wsq, demod                                             */
/* ------------------------------------------------------------------ */
__global__ void style_kernel(const float* __restrict__ wl,
                             const float* __restrict__ fcw,
                             const float* __restrict__ fcb) {
    int b = blockIdx.x;
    int i = threadIdx.x;
    float acc = 0.f;
    for (int j = 0; j < WDIM; j++)
        acc = fmaf(wl[b * WDIM + j], fcw[j * CIN + i], acc);
    g_s[b * CIN + i] = acc * FC_COEF + fcb[i] + 1.0f;
}

__global__ void wsq_kernel(const float* __restrict__ w) {
    int idx = blockIdx.x * 256 + threadIdx.x;
    float acc = 0.f;
#pragma unroll
    for (int t9 = 0; t9 < 9; t9++) {
        float v = w[(size_t)t9 * CIN * COUT + idx];
        acc = fmaf(v, v, acc);
    }
    g_wsq[idx] = acc;
}

__global__ void demod_kernel() {
    int b = blockIdx.x;
    int co = threadIdx.x;
    float acc = 0.f;
    for (int ci = 0; ci < CIN; ci++) {
        float s = g_s[b * CIN + ci];
        acc = fmaf(s * s, g_wsq[ci * COUT + co], acc);
    }
    g_d[b * COUT + co] = rsqrtf(acc * CONV_COEF * CONV_COEF + 1e-8f);
}

/* ------------------------------------------------------------------ */
/* U = G (w*coef) G^T  (fp32)                                          */
/* ------------------------------------------------------------------ */
__global__ void u32_kernel(const float* __restrict__ w) {
    int idx = blockIdx.x * 256 + threadIdx.x;   /* 262144: (ci,co) */
    int co = idx & 511, ci = idx >> 9;
    float gm[3][3];
#pragma unroll
    for (int tap = 0; tap < 9; tap++)
        gm[tap / 3][tap % 3] = w[(size_t)tap * CIN * COUT + ci * COUT + co] * CONV_COEF;
    float T[4][3];
#pragma unroll
    for (int c = 0; c < 3; c++) {
        T[0][c] = gm[0][c];
        T[1][c] = 0.5f * (gm[0][c] + gm[1][c] + gm[2][c]);
        T[2][c] = 0.5f * (gm[0][c] - gm[1][c] + gm[2][c]);
        T[3][c] = gm[2][c];
    }
#pragma unroll
    for (int r = 0; r < 4; r++) {
        float u0 = T[r][0];
        float u1 = 0.5f * (T[r][0] + T[r][1] + T[r][2]);
        float u2 = 0.5f * (T[r][0] - T[r][1] + T[r][2]);
        float u3 = T[r][2];
        g_U32[(((size_t)(r * 4 + 0)) * 512 + ci) * 512 + co] = u0;
        g_U32[(((size_t)(r * 4 + 1)) * 512 + ci) * 512 + co] = u1;
        g_U32[(((size_t)(r * 4 + 2)) * 512 + ci) * 512 + co] = u2;
        g_U32[(((size_t)(r * 4 + 3)) * 512 + ci) * 512 + co] = u3;
    }
}

/* pack U into m16n8k16 B-fragment order:
   uint4 idx = (((((pos*4+nblk)*16+ck)*2+kg)*2+wN)*4+q)*32+lane         */
__global__ void upack_kernel() {
    int idx = blockIdx.x * 256 + threadIdx.x;   /* 524288 uint4 */
    int lane = idx & 31;
    int r = idx >> 5;
    int q  = r & 3;  r >>= 2;
    int wN = r & 1;  r >>= 1;
    int kg = r & 1;  r >>= 1;
    int ck = r & 15; r >>= 4;
    int nblk = r & 3;
    int pos  = r >> 2;
    int n  = nblk * 128 + wN * 64 + q * 16 + (lane >> 2);
    int k0 = ck * 32 + kg * 16 + 2 * (lane & 3);
    const float* up = g_U32 + (size_t)pos * 512 * 512;
    uint4 o;
    o.x = h2u(__floats2half2_rn(up[(size_t)k0 * 512 + n],       up[(size_t)(k0 + 1) * 512 + n]));
    o.y = h2u(__floats2half2_rn(up[(size_t)(k0 + 8) * 512 + n], up[(size_t)(k0 + 9) * 512 + n]));
    o.z = h2u(__floats2half2_rn(up[(size_t)k0 * 512 + n + 8],   up[(size_t)(k0 + 1) * 512 + n + 8]));
    o.w = h2u(__floats2half2_rn(up[(size_t)(k0 + 8) * 512 + n + 8], up[(size_t)(k0 + 9) * 512 + n + 8]));
    ((uint4*)g_U)[idx] = o;
}

/* ------------------------------------------------------------------ */
/* V = B^T (x*s) B : per (mblk of 16 tiles, 32-ch group)               */
/* ------------------------------------------------------------------ */
__global__ void v_kernel(const float* __restrict__ x) {
    __shared__ __half sbuf[16 * 2 * 256];       /* 16KB: [pos][kg][512B] */
    const int bx = blockIdx.x;
    const int mblk = bx >> 4, ckg = bx & 15;
    const int b  = mblk >> 6;
    const int ml = mblk & 63;
    const int ty = ml >> 1;
    const int tx0 = (ml & 1) * 16;
    const int tid = threadIdx.x;

#pragma unroll
    for (int u = 0; u < 2; u++) {
        int uid = tid + 256 * u;
        int tl = uid >> 5, ch = uid & 31;
        int ci = ckg * 32 + ch;
        float s = g_s[b * 512 + ci];
        int tx = tx0 + tl;
        int iy0 = 2 * ty - 1, ix0 = 2 * tx - 1;
        float d[4][4];
#pragma unroll
        for (int r = 0; r < 4; r++) {
            int iy = iy0 + r;
            bool vy = (unsigned)iy < HW;
#pragma unroll
            for (int c = 0; c < 4; c++) {
                int ix = ix0 + c;
                d[r][c] = (vy && (unsigned)ix < HW)
                          ? x[((size_t)((b * HW + iy) * HW + ix)) * CIN + ci] * s
                          : 0.f;
            }
        }
        float tt[4][4];
#pragma unroll
        for (int c = 0; c < 4; c++) {
            tt[0][c] = d[0][c] - d[2][c];
            tt[1][c] = d[1][c] + d[2][c];
            tt[2][c] = d[2][c] - d[1][c];
            tt[3][c] = d[1][c] - d[3][c];
        }
        int g = tl & 7, h = tl >> 3;
        int kg = ch >> 4, kk = ch & 15, j = kk >> 1;
        int off = g * 64 + (j & 3) * 16 + (j >> 2) * 8 + h * 4 + (kk & 1) * 2;
#pragma unroll
        for (int i = 0; i < 4; i++) {
            float v0 = tt[i][0] - tt[i][2];
            float v1 = tt[i][1] + tt[i][2];
            float v2 = tt[i][2] - tt[i][1];
            float v3 = tt[i][1] - tt[i][3];
            char* pl = (char*)sbuf + kg * 512;
            *(__half*)(pl + (i * 4 + 0) * 1024 + off) = __float2half(v0);
            *(__half*)(pl + (i * 4 + 1) * 1024 + off) = __float2half(v1);
            *(__half*)(pl + (i * 4 + 2) * 1024 + off) = __float2half(v2);
            *(__half*)(pl + (i * 4 + 3) * 1024 + off) = __float2half(v3);
        }
    }
    __syncthreads();
#pragma unroll
    for (int j = 0; j < 4; j++) {
        int cidx = tid + 256 * j;
        int plane = cidx >> 5, o16 = (cidx & 31) * 16;
        int pos = plane >> 1, kg = plane & 1;
        char* dst = (char*)g_V + (((size_t)(pos * 32 + ckg * 2 + kg)) * 1024 + mblk) * 512 + o16;
        *(uint4*)dst = *(uint4*)((char*)sbuf + plane * 512 + o16);
    }
}

/* ------------------------------------------------------------------ */
/* GEMM per pos: M[m 16384][n 512] = V U ; CTA 128x128, warp 64x32     */
/* ------------------------------------------------------------------ */
#define GSTG 16384

__device__ __forceinline__ void g_load(uint32_t sb, const char* Vsrc, const char* Usrc,
                                       int ck, int tid) {
#pragma unroll
    for (int j = 0; j < 4; j++) {
        int i = tid + 256 * j;
        if (i < 512) {
            int kg = i >> 8, mo = i & 255;
            const char* src = Vsrc + ((size_t)(ck * 2 + kg) * 1024 + (mo >> 5)) * 512 + (mo & 31) * 16;
            cp16(sb + kg * 4096 + mo * 16, src);
        } else {
            int i2 = i - 512;
            cp16(sb + 8192 + i2 * 16, Usrc + (size_t)ck * 8192 + i2 * 16);
        }
    }
}

__global__ __launch_bounds__(256, 2)
void gemm_kernel() {
    extern __shared__ char sm[];
    const int tid  = threadIdx.x;
    const int warp = tid >> 5;
    const int lane = tid & 31;
    const int g = lane >> 2, t = lane & 3;
    const int wn = warp & 3, wm = warp >> 2;
    const int nblk = blockIdx.x;
    const int mby  = blockIdx.y;
    const int pos  = blockIdx.z;

    const char* Vsrc = (const char*)g_V + ((size_t)pos * 32 * 1024 + (size_t)mby * 8) * 512;
    const char* Usrc = (const char*)g_U + (size_t)((pos * 4 + nblk) * 16) * 8192;
    const uint32_t sb = su32(sm);

    float acc[4][4][4];
#pragma unroll
    for (int mi = 0; mi < 4; mi++)
#pragma unroll
        for (int ni = 0; ni < 4; ni++)
#pragma unroll
            for (int r = 0; r < 4; r++) acc[mi][ni][r] = 0.f;

    g_load(sb, Vsrc, Usrc, 0, tid); cp_commit();
    g_load(sb + GSTG, Vsrc, Usrc, 1, tid); cp_commit();
    g_load(sb + 2 * GSTG, Vsrc, Usrc, 2, tid); cp_commit();

    for (int s = 0; s < 16; s++) {
        cp_wait<2>();
        __syncthreads();
        if (s + 3 < 16)
            g_load(sb + ((s + 3) & 3) * GSTG, Vsrc, Usrc, s + 3, tid);
        cp_commit();

        const char* st = sm + (s & 3) * GSTG;
#pragma unroll
        for (int kg = 0; kg < 2; kg++) {
            const char* ab = st + kg * 4096 + (wm * 4) * 512 + g * 64 + t * 16;
            float4 Af[4];
#pragma unroll
            for (int mi = 0; mi < 4; mi++)
                Af[mi] = *(const float4*)(ab + mi * 512);
            const char* bb = st + 8192 + kg * 4096 + (wn >> 1) * 2048 + (wn & 1) * 1024 + lane * 16;
            float4 Bf[2];
            Bf[0] = *(const float4*)bb;
            Bf[1] = *(const float4*)(bb + 512);
#pragma unroll
            for (int mi = 0; mi < 4; mi++)
#pragma unroll
                for (int ni = 0; ni < 4; ni++) {
                    const float4& B = Bf[ni >> 1];
                    uint32_t b0 = __float_as_uint((ni & 1) ? B.z : B.x);
                    uint32_t b1 = __float_as_uint((ni & 1) ? B.w : B.y);
                    mma16(acc[mi][ni],
                          __float_as_uint(Af[mi].x), __float_as_uint(Af[mi].y),
                          __float_as_uint(Af[mi].z), __float_as_uint(Af[mi].w),
                          b0, b1);
                }
        }
    }

    float* Mp = g_M + (size_t)pos * NTILE * 512;
    const int m0 = mby * 128 + wm * 64;
    const int c0 = nblk * 128 + wn * 32;
#pragma unroll
    for (int mi = 0; mi < 4; mi++) {
        int r0 = m0 + mi * 16 + g;
#pragma unroll
        for (int ni = 0; ni < 4; ni++) {
            int cc = c0 + (ni >> 1) * 16 + (ni & 1) * 8 + t * 2;
            *(float2*)(Mp + (size_t)r0 * 512 + cc)       = make_float2(acc[mi][ni][0], acc[mi][ni][1]);
            *(float2*)(Mp + (size_t)(r0 + 8) * 512 + cc) = make_float2(acc[mi][ni][2], acc[mi][ni][3]);
        }
    }
}

/* ------------------------------------------------------------------ */
/* inverse transform: y = A^T M A, * demod + bias                      */
/* ------------------------------------------------------------------ */
__global__ void inv_kernel(const float* __restrict__ bias, float* __restrict__ out) {
    int Wu = blockIdx.x * 8 + (threadIdx.x >> 5);
    int lane = threadIdx.x & 31;
    int tile = Wu >> 4, cog = Wu & 15;
    int co = cog * 32 + lane;
    int b = tile >> 10, tl = tile & 1023, ty = tl >> 5, tx = tl & 31;

    float M[16];
#pragma unroll
    for (int pos = 0; pos < 16; pos++)
        M[pos] = g_M[((size_t)pos * NTILE + tile) * 512 + co];

    float P0[4], P1[4];
#pragma unroll
    for (int r = 0; r < 4; r++) {
        P0[r] = M[r * 4 + 0] + M[r * 4 + 1] + M[r * 4 + 2];
        P1[r] = M[r * 4 + 1] - M[r * 4 + 2] - M[r * 4 + 3];
    }
    float y00 = P0[0] + P0[1] + P0[2];
    float y10 = P0[1] - P0[2] - P0[3];
    float y01 = P1[0] + P1[1] + P1[2];
    float y11 = P1[1] - P1[2] - P1[3];

    float dd = g_d[b * 512 + co];
    float bb = bias[co];
    int Y = 2 * ty, X = 2 * tx;
    float* o = out + ((size_t)((b * HW + Y) * HW + X)) * 512 + co;
    o[0]              = y00 * dd + bb;
    o[512]            = y01 * dd + bb;
    o[HW * 512]       = y10 * dd + bb;
    o[HW * 512 + 512] = y11 * dd + bb;
}

/* ------------------------------------------------------------------ */
extern "C" void kernel_launch(void* const* d_in, const int* in_sizes, int n_in,
                              void* d_out, int out_size) {
    (void)in_sizes; (void)n_in; (void)out_size;
    const float* x    = (const float*)d_in[0];
    const float* wl   = (const float*)d_in[1];
    const float* w    = (const float*)d_in[2];
    const float* bias = (const float*)d_in[3];
    const float* fcw  = (const float*)d_in[4];
    const float* fcb  = (const float*)d_in[5];
    float* out = (float*)d_out;

    style_kernel<<<NB, CIN>>>(wl, fcw, fcb);
    u32_kernel<<<1024, 256>>>(w);
    upack_kernel<<<2048, 256>>>();        /* 524288 uint4 / 256  (R7 bug: was 1024) */
    wsq_kernel<<<1024, 256>>>(w);
    demod_kernel<<<NB, COUT>>>();
    v_kernel<<<16384, 256>>>(x);

    cudaFuncSetAttribute(gemm_kernel, cudaFuncAttributeMaxDynamicSharedMemorySize, 4 * GSTG);
    gemm_kernel<<<dim3(4, 128, 16), 256, 4 * GSTG>>>();

    inv_kernel<<<32768, 256>>>(bias, out);
}